// round 12
// baseline (speedup 1.0000x reference)
#include <cuda_runtime.h>
#include <cstdint>

// out[b,h,w,c] = (vector[0,c] >= -5) ? ip1[b,h,w,c] : ip2[b,h,w,c]
// Fixed shape: 16,777,216 f32 = 64 MiB per tensor.
//
// R12: TMA bulk-copy path. Each block copies two 16 KiB contiguous chunks of
// the selected source (ip1 if all 128 channel masks true, ip2 if all false)
// via cp.async.bulk GMEM->SMEM (mbarrier) then SMEM->GMEM (bulk_group),
// double-buffered. A 16 KiB chunk = 32 rows x 128 channels, so the block-level
// select is valid whenever the mask is uniform (probability ~1 for N(0,1));
// the mixed case falls back to an elementwise float4 loop.
// 2048 blocks x 32 KiB = 64 MiB exactly. Static smem 32 KiB + barriers.

static constexpr int THREADS = 128;
static constexpr int CHUNK = 16 * 1024;              // bytes per bulk op
static constexpr int BLK_BYTES = 2 * CHUNK;          // 32 KiB per block
static constexpr int BLOCKS = (64 * 1024 * 1024) / BLK_BYTES;  // 2048
static constexpr int N4_PER_BLOCK = BLK_BYTES / 16;  // 2048 float4

__device__ __forceinline__ uint32_t smem_u32(const void* p) {
    uint32_t a;
    asm("{ .reg .u64 t; cvta.to.shared.u64 t, %1; cvt.u32.u64 %0, t; }"
        : "=r"(a) : "l"(p));
    return a;
}

__device__ __forceinline__ void mbar_init(uint32_t mbar, uint32_t cnt) {
    asm volatile("mbarrier.init.shared.b64 [%0], %1;" :: "r"(mbar), "r"(cnt) : "memory");
}
__device__ __forceinline__ void mbar_expect_tx(uint32_t mbar, uint32_t bytes) {
    asm volatile("mbarrier.arrive.expect_tx.shared.b64 _, [%0], %1;"
                 :: "r"(mbar), "r"(bytes) : "memory");
}
__device__ __forceinline__ void mbar_wait(uint32_t mbar) {
    asm volatile(
        "{\n\t"
        ".reg .pred P;\n\t"
        "WAIT_%=:\n\t"
        "mbarrier.try_wait.parity.shared.b64 P, [%0], 0, 0x989680;\n\t"
        "@P bra.uni DONE_%=;\n\t"
        "bra.uni WAIT_%=;\n\t"
        "DONE_%=:\n\t"
        "}" :: "r"(mbar) : "memory");
}
__device__ __forceinline__ void bulk_g2s(uint32_t dst_smem, const void* src, uint32_t bytes, uint32_t mbar) {
    asm volatile("cp.async.bulk.shared::cta.global.mbarrier::complete_tx::bytes [%0], [%1], %2, [%3];"
                 :: "r"(dst_smem), "l"(src), "r"(bytes), "r"(mbar) : "memory");
}
__device__ __forceinline__ void bulk_s2g(void* dst, uint32_t src_smem, uint32_t bytes) {
    asm volatile("cp.async.bulk.global.shared::cta.bulk_group [%0], [%1], %2;"
                 :: "l"(dst), "r"(src_smem), "r"(bytes) : "memory");
}

__global__ __launch_bounds__(THREADS)
void random_pick_kernel(const float* __restrict__ ip1,
                        const float* __restrict__ ip2,
                        const float* __restrict__ vec,
                        float* __restrict__ out)
{
    __shared__ __align__(128) char buf[2 * CHUNK];
    __shared__ __align__(8) uint64_t mbar_storage[2];

    int tid = threadIdx.x;

    // Full 128-channel mask: one channel per thread.
    bool mi = vec[tid] >= -5.0f;
    bool all  = __syncthreads_and(mi);
    bool none = __syncthreads_and(!mi);

    if (all | none) {
        // Hot path: bulk copy of the selected source.
        const float* src = all ? ip1 : ip2;
        size_t off = (size_t)blockIdx.x * BLK_BYTES;  // byte offset

        uint32_t sbuf = smem_u32(buf);
        uint32_t mb0 = smem_u32(&mbar_storage[0]);
        uint32_t mb1 = smem_u32(&mbar_storage[1]);

        if (tid == 0) {
            mbar_init(mb0, 1);
            mbar_init(mb1, 1);
        }
        __syncthreads();

        if (tid == 0) {
            const char* s = reinterpret_cast<const char*>(src) + off;
            char* d = reinterpret_cast<char*>(out) + off;

            mbar_expect_tx(mb0, CHUNK);
            bulk_g2s(sbuf, s, CHUNK, mb0);
            mbar_expect_tx(mb1, CHUNK);
            bulk_g2s(sbuf + CHUNK, s + CHUNK, CHUNK, mb1);

            mbar_wait(mb0);
            asm volatile("fence.proxy.async.shared::cta;" ::: "memory");
            bulk_s2g(d, sbuf, CHUNK);
            asm volatile("cp.async.bulk.commit_group;" ::: "memory");

            mbar_wait(mb1);
            asm volatile("fence.proxy.async.shared::cta;" ::: "memory");
            bulk_s2g(d + CHUNK, sbuf + CHUNK, CHUNK);
            asm volatile("cp.async.bulk.commit_group;" ::: "memory");

            asm volatile("cp.async.bulk.wait_group 0;" ::: "memory");
        }
    } else {
        // Mixed mask (astronomically rare): elementwise float4 select.
        const float4* a4 = reinterpret_cast<const float4*>(ip1);
        const float4* b4 = reinterpret_cast<const float4*>(ip2);
        const float4* v4 = reinterpret_cast<const float4*>(vec);
        float4* o4 = reinterpret_cast<float4*>(out);
        size_t base4 = (size_t)blockIdx.x * N4_PER_BLOCK;
        for (int i = tid; i < N4_PER_BLOCK; i += THREADS) {
            size_t j = base4 + i;
            int cg = (int)(j & 31);  // float4 channel group
            float4 v = v4[cg];
            float4 a = a4[j];
            float4 b = b4[j];
            float4 r;
            r.x = (v.x >= -5.0f) ? a.x : b.x;
            r.y = (v.y >= -5.0f) ? a.y : b.y;
            r.z = (v.z >= -5.0f) ? a.z : b.z;
            r.w = (v.w >= -5.0f) ? a.w : b.w;
            o4[j] = r;
        }
    }
}

extern "C" void kernel_launch(void* const* d_in, const int* in_sizes, int n_in,
                              void* d_out, int out_size)
{
    const float* ip1 = reinterpret_cast<const float*>(d_in[0]);
    const float* ip2 = reinterpret_cast<const float*>(d_in[1]);
    const float* vec = reinterpret_cast<const float*>(d_in[2]);  // row 0 used
    float* out = reinterpret_cast<float*>(d_out);

    random_pick_kernel<<<BLOCKS, THREADS>>>(ip1, ip2, vec, out);
}

// round 13
// speedup vs baseline: 1.0962x; 1.0962x over previous
#include <cuda_runtime.h>
#include <cstdint>

// out[b,h,w,c] = (vector[0,c] >= -5) ? ip1[b,h,w,c] : ip2[b,h,w,c]
// Fixed shape: 16,777,216 f32 = 4,194,304 float4 = 2048 blocks x 256 thr x 8.
//
// FINAL (R7 winner, best kernel time 17.79us): the mandatory 64 MiB read +
// 64 MiB write mixed stream is at the DRAM/LTS turnaround equilibrium; LDG,
// 256-bit LDG and TMA bulk all converge to ~18-19us (path-independent), and
// the full cache-policy matrix (cs/cg/wb/wt/evict hints) is flat. Winning
// structure:
//   - exact tiling, no bounds checks (shape is compile-time fixed)
//   - 8 speculative __ldcg loads issued BEFORE the mask resolves (removes the
//     vec-load -> branch -> data-load serial chain; mask ~always selects ip1)
//   - plain .wb stores (best-measured store policy)
//   - thread stride 256 == 0 mod 32 -> fixed float4 channel group per thread

static constexpr int THREADS = 256;
static constexpr int VPT = 8;                       // float4 per thread
static constexpr int N4 = 32 * 64 * 64 * 128 / 4;   // 4,194,304
static constexpr int BLOCKS = N4 / (THREADS * VPT); // 2048, exact

__global__ __launch_bounds__(THREADS)
void random_pick_kernel(const float4* __restrict__ ip1,
                        const float4* __restrict__ ip2,
                        const float* __restrict__ vec,
                        float4* __restrict__ out)
{
    int base = blockIdx.x * (THREADS * VPT) + threadIdx.x;
    int g = base & 31;  // fixed channel group (stride 256 == 0 mod 32)

    // Speculative: issue all 8 data loads immediately; mask load overlaps.
    float4 r[VPT];
    #pragma unroll
    for (int i = 0; i < VPT; i++)
        r[i] = __ldcg(ip1 + base + i * THREADS);

    float4 v = __ldg(reinterpret_cast<const float4*>(vec) + g);
    bool m0 = v.x >= -5.0f;
    bool m1 = v.y >= -5.0f;
    bool m2 = v.z >= -5.0f;
    bool m3 = v.w >= -5.0f;

    if (!(m0 & m1 & m2 & m3)) {
        // Cold path (probability ~0 for N(0,1) vector).
        if (!(m0 | m1 | m2 | m3)) {
            #pragma unroll
            for (int i = 0; i < VPT; i++)
                r[i] = __ldcg(ip2 + base + i * THREADS);
        } else {
            #pragma unroll
            for (int i = 0; i < VPT; i++) {
                float4 b = __ldcg(ip2 + base + i * THREADS);
                r[i].x = m0 ? r[i].x : b.x;
                r[i].y = m1 ? r[i].y : b.y;
                r[i].z = m2 ? r[i].z : b.z;
                r[i].w = m3 ? r[i].w : b.w;
            }
        }
    }

    // Plain .wb stores (best-measured policy).
    #pragma unroll
    for (int i = 0; i < VPT; i++)
        out[base + i * THREADS] = r[i];
}

extern "C" void kernel_launch(void* const* d_in, const int* in_sizes, int n_in,
                              void* d_out, int out_size)
{
    const float4* ip1 = reinterpret_cast<const float4*>(d_in[0]);
    const float4* ip2 = reinterpret_cast<const float4*>(d_in[1]);
    const float*  vec = reinterpret_cast<const float*>(d_in[2]);  // row 0 used
    float4* out = reinterpret_cast<float4*>(d_out);

    random_pick_kernel<<<BLOCKS, THREADS>>>(ip1, ip2, vec, out);
}